// round 7
// baseline (speedup 1.0000x reference)
#include <cuda_runtime.h>
#include <cuda_bf16.h>
#include <math.h>
#include <stdint.h>

// Problem constants
#define BB   4
#define SS   2048
#define DD   1024
#define HH   16
#define HD   64
#define MR   (BB * SS)          // 8192 rows

// 0.125 * log2(e): folded softmax scale, base-2 domain
#define SCALE_LG2 0.18033688011112042f

// ---------------------------------------------------------------------------
// Scratch (device globals; no allocation allowed)
// ---------------------------------------------------------------------------
__device__ __nv_bfloat16 g_xh[8388608],  g_xl[8388608];
__device__ __nv_bfloat16 g_wqh[1048576], g_wql[1048576];
__device__ __nv_bfloat16 g_wkh[1048576], g_wkl[1048576];
__device__ __nv_bfloat16 g_wvh[1048576], g_wvl[1048576];
__device__ __nv_bfloat16 g_woh[1048576], g_wol[1048576];
__device__ __nv_bfloat16 g_qh[8388608], g_ql[8388608];
__device__ __nv_bfloat16 g_kh[8388608], g_kl[8388608];
__device__ __nv_bfloat16 g_vh[8388608], g_vl[8388608];
__device__ __nv_bfloat16 g_ath[8388608], g_atl[8388608];

// ---------------------------------------------------------------------------
// Helpers (plain sm_103-legal PTX: ldmatrix + mma.sync + cp.async)
// ---------------------------------------------------------------------------
__device__ __forceinline__ uint32_t smem_u32(const void* p) {
    uint32_t a;
    asm("{ .reg .u64 t; cvta.to.shared.u64 t, %1; cvt.u32.u64 %0, t; }" : "=r"(a) : "l"(p));
    return a;
}

__device__ __forceinline__ void ldmx4(uint32_t* r, uint32_t addr) {
    asm volatile("ldmatrix.sync.aligned.m8n8.x4.shared.b16 {%0,%1,%2,%3}, [%4];"
                 : "=r"(r[0]), "=r"(r[1]), "=r"(r[2]), "=r"(r[3]) : "r"(addr));
}

__device__ __forceinline__ void ldmx4t(uint32_t* r, uint32_t addr) {
    asm volatile("ldmatrix.sync.aligned.m8n8.x4.trans.shared.b16 {%0,%1,%2,%3}, [%4];"
                 : "=r"(r[0]), "=r"(r[1]), "=r"(r[2]), "=r"(r[3]) : "r"(addr));
}

__device__ __forceinline__ void mma_bf16(float* c, const uint32_t* a,
                                         uint32_t b0, uint32_t b1) {
    asm volatile(
        "mma.sync.aligned.m16n8k16.row.col.f32.bf16.bf16.f32 "
        "{%0,%1,%2,%3}, {%4,%5,%6,%7}, {%8,%9}, {%0,%1,%2,%3};"
        : "+f"(c[0]), "+f"(c[1]), "+f"(c[2]), "+f"(c[3])
        : "r"(a[0]), "r"(a[1]), "r"(a[2]), "r"(a[3]), "r"(b0), "r"(b1));
}

__device__ __forceinline__ void cpa16(uint32_t s, const void* g) {
    asm volatile("cp.async.ca.shared.global [%0], [%1], 16;" :: "r"(s), "l"(g) : "memory");
}
#define CPA_COMMIT() asm volatile("cp.async.commit_group;" ::: "memory")
#define CPA_WAIT0()  asm volatile("cp.async.wait_group 0;" ::: "memory")

__device__ __forceinline__ uint32_t pack_bf16(float x, float y) {
    __nv_bfloat162 t = __floats2bfloat162_rn(x, y);
    return *reinterpret_cast<uint32_t*>(&t);
}

// ---------------------------------------------------------------------------
// Split kernel: fp32 -> bf16 hi/lo (grid-stride over float4)
// ---------------------------------------------------------------------------
__global__ void split_fp32(const float* __restrict__ src,
                           __nv_bfloat16* __restrict__ hi,
                           __nv_bfloat16* __restrict__ lo, int n4)
{
    int i = blockIdx.x * blockDim.x + threadIdx.x;
    if (i >= n4) return;
    float4 v = reinterpret_cast<const float4*>(src)[i];
    __nv_bfloat162 h01 = __floats2bfloat162_rn(v.x, v.y);
    __nv_bfloat162 h23 = __floats2bfloat162_rn(v.z, v.w);
    __nv_bfloat162 l01 = __floats2bfloat162_rn(v.x - __bfloat162float(h01.x),
                                               v.y - __bfloat162float(h01.y));
    __nv_bfloat162 l23 = __floats2bfloat162_rn(v.z - __bfloat162float(h23.x),
                                               v.w - __bfloat162float(h23.y));
    uint2 hh = make_uint2(*reinterpret_cast<uint32_t*>(&h01), *reinterpret_cast<uint32_t*>(&h23));
    uint2 ll = make_uint2(*reinterpret_cast<uint32_t*>(&l01), *reinterpret_cast<uint32_t*>(&l23));
    reinterpret_cast<uint2*>(hi)[i] = hh;
    reinterpret_cast<uint2*>(lo)[i] = ll;
}

// ---------------------------------------------------------------------------
// Pure-bf16 split HMMA GEMM: C = A @ B^T with A=(Ah+Al), B=(Bh+Bl).
// D += Ah*Bh + Ah*Bl + Al*Bh. cp.async 2-stage pipeline. 512 thr, 2 CTA/SM.
// CTA tile 128x128, K-tile 32.
// ---------------------------------------------------------------------------
#define GKP 40                        // padded row: 32 bf16 + 8 pad (80B)
#define GT  (128 * GKP)               // elems per tile
#define GSTAGE (4 * GT)               // Ah, Al, Bh, Bl
#define GEMM_SMEM (2 * GSTAGE * 2)    // 81920 B

#define GEMM_BF_BODY()                                                         \
    extern __shared__ __align__(16) char smem_raw[];                           \
    const uint32_t sb = smem_u32(smem_raw);                                    \
    const int tid  = threadIdx.x;                                              \
    const int lane = tid & 31;                                                 \
    const int wid  = tid >> 5;                                                 \
    const int wm   = wid >> 2;                                                 \
    const int wn   = wid & 3;                                                  \
    const int bm   = blockIdx.x * 128;                                         \
    const int bn   = blockIdx.y * 128;                                         \
    /* copy task: 4 tiles x 128 rows, one row per thread */                    \
    const int ctile = tid >> 7;                                                \
    const int crow  = tid & 127;                                               \
    const __nv_bfloat16* csrc =                                                \
        (ctile == 0) ? Ah + (size_t)(bm + crow) * DD :                         \
        (ctile == 1) ? Al + (size_t)(bm + crow) * DD :                         \
        (ctile == 2) ? Bh + (size_t)(bn + crow) * DD :                         \
                       Bl + (size_t)(bn + crow) * DD;                          \
    const uint32_t cdst0 = sb + (uint32_t)(ctile * GT + crow * GKP) * 2;       \
    const uint32_t aoffB =                                                     \
        (uint32_t)(((wm * 32 + (lane & 15)) * GKP + (lane >> 4) * 8) * 2);     \
    const uint32_t boffB =                                                     \
        (uint32_t)(((wn * 32 + ((lane >> 4) << 3) + (lane & 7)) * GKP +        \
                    ((lane >> 3) & 1) * 8) * 2);                               \
    float acc[2][4][4];                                                        \
    _Pragma("unroll")                                                          \
    for (int mt = 0; mt < 2; mt++)                                             \
        _Pragma("unroll")                                                      \
        for (int nt = 0; nt < 4; nt++)                                         \
            _Pragma("unroll")                                                  \
            for (int i = 0; i < 4; i++) acc[mt][nt][i] = 0.f;                  \
    /* prologue: issue stage 0 */                                              \
    {                                                                          \
        const __nv_bfloat16* g = csrc;                                         \
        _Pragma("unroll")                                                      \
        for (int i = 0; i < 4; i++) cpa16(cdst0 + i * 16, g + i * 8);          \
        CPA_COMMIT();                                                          \
    }                                                                          \
    _Pragma("unroll 1")                                                        \
    for (int kt = 0; kt < 32; kt++) {                                          \
        const int buf = kt & 1;                                                \
        CPA_WAIT0();                                                           \
        __syncthreads();                                                       \
        if (kt + 1 < 32) {                                                     \
            const __nv_bfloat16* g = csrc + (kt + 1) * 32;                     \
            uint32_t d = cdst0 + (uint32_t)((buf ^ 1) * GSTAGE * 2);           \
            _Pragma("unroll")                                                  \
            for (int i = 0; i < 4; i++) cpa16(d + i * 16, g + i * 8);          \
            CPA_COMMIT();                                                      \
        }                                                                      \
        const uint32_t tA_h = sb + (uint32_t)(buf * GSTAGE * 2);               \
        const uint32_t tA_l = tA_h + GT * 2;                                   \
        const uint32_t tB_h = tA_h + 2 * GT * 2;                               \
        const uint32_t tB_l = tA_h + 3 * GT * 2;                               \
        _Pragma("unroll")                                                      \
        for (int ks = 0; ks < 2; ks++) {                                       \
            const uint32_t kb = ks * 32;                                       \
            uint32_t ah[2][4], al[2][4], bh[2][4], bl[2][4];                   \
            _Pragma("unroll")                                                  \
            for (int mt = 0; mt < 2; mt++) {                                   \
                ldmx4(ah[mt], tA_h + aoffB + mt * (16 * GKP * 2) + kb);        \
                ldmx4(al[mt], tA_l + aoffB + mt * (16 * GKP * 2) + kb);        \
            }                                                                  \
            _Pragma("unroll")                                                  \
            for (int nt2 = 0; nt2 < 2; nt2++) {                                \
                ldmx4(bh[nt2], tB_h + boffB + nt2 * (16 * GKP * 2) + kb);      \
                ldmx4(bl[nt2], tB_l + boffB + nt2 * (16 * GKP * 2) + kb);      \
            }                                                                  \
            _Pragma("unroll")                                                  \
            for (int mt = 0; mt < 2; mt++) {                                   \
                _Pragma("unroll")                                              \
                for (int nt2 = 0; nt2 < 2; nt2++) {                            \
                    _Pragma("unroll")                                          \
                    for (int h = 0; h < 2; h++) {                              \
                        float* c = acc[mt][nt2 * 2 + h];                       \
                        uint32_t b0h = bh[nt2][h * 2], b1h = bh[nt2][h * 2 + 1]; \
                        uint32_t b0l = bl[nt2][h * 2], b1l = bl[nt2][h * 2 + 1]; \
                        mma_bf16(c, ah[mt], b0h, b1h);                         \
                        mma_bf16(c, ah[mt], b0l, b1l);                         \
                        mma_bf16(c, al[mt], b0h, b1h);                         \
                    }                                                          \
                }                                                              \
            }                                                                  \
        }                                                                      \
        __syncthreads();                                                       \
    }

// fp32-output GEMM (final projection): A = att split, B = wo split
__global__ __launch_bounds__(512, 2)
void gemm_bf_f32(const __nv_bfloat16* __restrict__ Ah, const __nv_bfloat16* __restrict__ Al,
                 const __nv_bfloat16* __restrict__ Bh, const __nv_bfloat16* __restrict__ Bl,
                 float* __restrict__ C)
{
    GEMM_BF_BODY();
#pragma unroll
    for (int mt = 0; mt < 2; mt++) {
#pragma unroll
        for (int nt = 0; nt < 4; nt++) {
            int r = bm + wm * 32 + mt * 16 + (lane >> 2);
            int c = bn + wn * 32 + nt * 8 + (lane & 3) * 2;
            *(float2*)(C + (size_t)r * DD + c)       = make_float2(acc[mt][nt][0], acc[mt][nt][1]);
            *(float2*)(C + (size_t)(r + 8) * DD + c) = make_float2(acc[mt][nt][2], acc[mt][nt][3]);
        }
    }
}

// Fused QKV projection: blockIdx.z selects weight & split-bf16 output.
__global__ __launch_bounds__(512, 2)
void gemm_bf_qkv(const __nv_bfloat16* __restrict__ Xh, const __nv_bfloat16* __restrict__ Xl,
                 const __nv_bfloat16* __restrict__ Wqh, const __nv_bfloat16* __restrict__ Wql,
                 const __nv_bfloat16* __restrict__ Wkh, const __nv_bfloat16* __restrict__ Wkl,
                 const __nv_bfloat16* __restrict__ Wvh, const __nv_bfloat16* __restrict__ Wvl,
                 __nv_bfloat16* __restrict__ qh_, __nv_bfloat16* __restrict__ ql_,
                 __nv_bfloat16* __restrict__ kh_, __nv_bfloat16* __restrict__ kl_,
                 __nv_bfloat16* __restrict__ vh_, __nv_bfloat16* __restrict__ vl_)
{
    const __nv_bfloat16 *Ah = Xh, *Al = Xl, *Bh, *Bl;
    __nv_bfloat16 *Chi, *Clo;
    float alpha = 1.0f;
    if (blockIdx.z == 0)      { Bh = Wqh; Bl = Wql; Chi = qh_; Clo = ql_; alpha = SCALE_LG2; }
    else if (blockIdx.z == 1) { Bh = Wkh; Bl = Wkl; Chi = kh_; Clo = kl_; }
    else                      { Bh = Wvh; Bl = Wvl; Chi = vh_; Clo = vl_; }

    GEMM_BF_BODY();
#pragma unroll
    for (int mt = 0; mt < 2; mt++) {
#pragma unroll
        for (int nt = 0; nt < 4; nt++) {
            int r = bm + wm * 32 + mt * 16 + (lane >> 2);
            int c = bn + wn * 32 + nt * 8 + (lane & 3) * 2;
            float v0 = acc[mt][nt][0] * alpha, v1 = acc[mt][nt][1] * alpha;
            float v2 = acc[mt][nt][2] * alpha, v3 = acc[mt][nt][3] * alpha;
            uint32_t h01 = pack_bf16(v0, v1);
            uint32_t h23 = pack_bf16(v2, v3);
            __nv_bfloat162 hb01 = *reinterpret_cast<__nv_bfloat162*>(&h01);
            __nv_bfloat162 hb23 = *reinterpret_cast<__nv_bfloat162*>(&h23);
            uint32_t l01 = pack_bf16(v0 - __bfloat162float(hb01.x),
                                     v1 - __bfloat162float(hb01.y));
            uint32_t l23 = pack_bf16(v2 - __bfloat162float(hb23.x),
                                     v3 - __bfloat162float(hb23.y));
            *(uint32_t*)(Chi + (size_t)r * DD + c)       = h01;
            *(uint32_t*)(Chi + (size_t)(r + 8) * DD + c) = h23;
            *(uint32_t*)(Clo + (size_t)r * DD + c)       = l01;
            *(uint32_t*)(Clo + (size_t)(r + 8) * DD + c) = l23;
        }
    }
}

// ---------------------------------------------------------------------------
// Split-bf16 HMMA flash attention (R6-proven), epilogue writes split bf16.
// ---------------------------------------------------------------------------
#define AP 72
#define AT (64 * AP)
#define ATB (AT * 2)
#define ATTN_SMEM_BYTES (8 * ATB)     // 73728 -> 3 CTAs/SM

__global__ __launch_bounds__(128)
void attn_mma(const __nv_bfloat16* __restrict__ Qh, const __nv_bfloat16* __restrict__ Ql,
              const __nv_bfloat16* __restrict__ Kh, const __nv_bfloat16* __restrict__ Kl,
              const __nv_bfloat16* __restrict__ Vh, const __nv_bfloat16* __restrict__ Vl,
              __nv_bfloat16* __restrict__ ATh, __nv_bfloat16* __restrict__ ATl)
{
    extern __shared__ __align__(16) char asm_raw[];
    const uint32_t sb  = smem_u32(asm_raw);
    const uint32_t uQh = sb;
    const uint32_t uQl = sb + ATB;
    const uint32_t uKh = sb + 2 * ATB;
    const uint32_t uKl = sb + 3 * ATB;

    const int qb = (gridDim.x - 1) - blockIdx.x;   // heaviest first
    const int bh = blockIdx.y;
    const int b  = bh / HH;
    const int h  = bh % HH;
    const size_t base = (size_t)b * SS * DD + (size_t)h * HD;

    const int tid  = threadIdx.x;
    const int lane = tid & 31;
    const int w    = tid >> 5;

    const int comp = tid >> 6;
    const int crow = tid & 63;
    const __nv_bfloat16* Ksrc = comp ? Kl : Kh;
    const __nv_bfloat16* Vsrc = comp ? Vl : Vh;
    const uint32_t kdst = (comp ? uKl : uKh) + crow * AP * 2;
    const uint32_t rowoff = crow * AP * 2;

    {
        const __nv_bfloat16* src = comp ? Ql : Qh;
        const uint4* g = (const uint4*)(src + base + (size_t)(qb * 64 + crow) * DD);
        uint4* s = (uint4*)(asm_raw + comp * ATB + crow * AP * 2);
#pragma unroll
        for (int i = 0; i < 8; i++) s[i] = g[i];
    }
    {
        const __nv_bfloat16* gk = Ksrc + base + (size_t)crow * DD;
        const __nv_bfloat16* gv = Vsrc + base + (size_t)crow * DD;
        uint32_t vdst = sb + (4 + comp) * ATB + rowoff;
#pragma unroll
        for (int i = 0; i < 8; i++) cpa16(kdst + i * 16, gk + i * 8);
#pragma unroll
        for (int i = 0; i < 8; i++) cpa16(vdst + i * 16, gv + i * 8);
        CPA_COMMIT();
    }
    CPA_WAIT0();
    __syncthreads();

    const uint32_t aoff =
        (uint32_t)(((w * 16 + (lane & 15)) * AP + (lane >> 4) * 8) * 2);
    uint32_t qfh[4][4], qfl[4][4];
#pragma unroll
    for (int kk = 0; kk < 4; kk++) {
        ldmx4(qfh[kk], uQh + aoff + kk * 32);
        ldmx4(qfl[kk], uQl + aoff + kk * 32);
    }

    const uint32_t boff =
        (uint32_t)(((((lane >> 4) << 3) + (lane & 7)) * AP + ((lane >> 3) & 1) * 8) * 2);
    const uint32_t voff =
        (uint32_t)((((lane & 7) + ((lane >> 3) & 1) * 8) * AP) * 2 + (lane >> 4) * 16);

    const int r0  = lane >> 2;
    const int qg0 = qb * 64 + w * 16 + r0;
    const int qg1 = qg0 + 8;

    float m0 = -INFINITY, m1 = -INFINITY, l0 = 0.f, l1 = 0.f;
    float oacc[8][4];
#pragma unroll
    for (int nt = 0; nt < 8; nt++)
#pragma unroll
        for (int i = 0; i < 4; i++) oacc[nt][i] = 0.f;

#pragma unroll 1
    for (int jb = 0; jb <= qb; jb++) {
        const int vb = jb & 1;

        if (jb < qb) {
            const __nv_bfloat16* gv = Vsrc + base + (size_t)((jb + 1) * 64 + crow) * DD;
            uint32_t vdst = sb + (4 + 2 * (vb ^ 1) + comp) * ATB + rowoff;
#pragma unroll
            for (int i = 0; i < 8; i++) cpa16(vdst + i * 16, gv + i * 8);
            CPA_COMMIT();
        }

        float sacc[8][4];
#pragma unroll
        for (int nt = 0; nt < 8; nt++)
#pragma unroll
            for (int i = 0; i < 4; i++) sacc[nt][i] = 0.f;

#pragma unroll
        for (int kk = 0; kk < 4; kk++) {
            const uint32_t kb = kk * 32;
#pragma unroll
            for (int np = 0; np < 4; np++) {
                const uint32_t nb = (uint32_t)(np * 16 * AP * 2);
                uint32_t kh[4], kl[4];
                ldmx4(kh, uKh + boff + nb + kb);
                ldmx4(kl, uKl + boff + nb + kb);
#pragma unroll
                for (int hh = 0; hh < 2; hh++) {
                    float* c = sacc[np * 2 + hh];
                    mma_bf16(c, qfh[kk], kh[hh * 2], kh[hh * 2 + 1]);
                    mma_bf16(c, qfl[kk], kh[hh * 2], kh[hh * 2 + 1]);
                    mma_bf16(c, qfh[kk], kl[hh * 2], kl[hh * 2 + 1]);
                }
            }
        }
        __syncthreads();

        if (jb < qb) {
            const __nv_bfloat16* gk = Ksrc + base + (size_t)((jb + 1) * 64 + crow) * DD;
#pragma unroll
            for (int i = 0; i < 8; i++) cpa16(kdst + i * 16, gk + i * 8);
            CPA_COMMIT();
        }

        const int kvb = jb * 64 + (lane & 3) * 2;
        float mx0 = -INFINITY, mx1 = -INFINITY;
#pragma unroll
        for (int nt = 0; nt < 8; nt++) {
            int kg = kvb + nt * 8;
            float s0 = sacc[nt][0]; if (kg     > qg0) s0 = -INFINITY;
            float s1 = sacc[nt][1]; if (kg + 1 > qg0) s1 = -INFINITY;
            float s2 = sacc[nt][2]; if (kg     > qg1) s2 = -INFINITY;
            float s3 = sacc[nt][3]; if (kg + 1 > qg1) s3 = -INFINITY;
            sacc[nt][0] = s0; sacc[nt][1] = s1; sacc[nt][2] = s2; sacc[nt][3] = s3;
            mx0 = fmaxf(mx0, fmaxf(s0, s1));
            mx1 = fmaxf(mx1, fmaxf(s2, s3));
        }
        mx0 = fmaxf(mx0, __shfl_xor_sync(0xffffffff, mx0, 1));
        mx0 = fmaxf(mx0, __shfl_xor_sync(0xffffffff, mx0, 2));
        mx1 = fmaxf(mx1, __shfl_xor_sync(0xffffffff, mx1, 1));
        mx1 = fmaxf(mx1, __shfl_xor_sync(0xffffffff, mx1, 2));

        float mn0 = fmaxf(m0, mx0), mn1 = fmaxf(m1, mx1);
        float sc0 = exp2f(m0 - mn0), sc1 = exp2f(m1 - mn1);
        float sum0 = 0.f, sum1 = 0.f;
#pragma unroll
        for (int nt = 0; nt < 8; nt++) {
            float p0 = exp2f(sacc[nt][0] - mn0);
            float p1 = exp2f(sacc[nt][1] - mn0);
            float p2 = exp2f(sacc[nt][2] - mn1);
            float p3 = exp2f(sacc[nt][3] - mn1);
            sacc[nt][0] = p0; sacc[nt][1] = p1; sacc[nt][2] = p2; sacc[nt][3] = p3;
            sum0 += p0 + p1; sum1 += p2 + p3;
        }
        sum0 += __shfl_xor_sync(0xffffffff, sum0, 1);
        sum0 += __shfl_xor_sync(0xffffffff, sum0, 2);
        sum1 += __shfl_xor_sync(0xffffffff, sum1, 1);
        sum1 += __shfl_xor_sync(0xffffffff, sum1, 2);
        l0 = l0 * sc0 + sum0;  l1 = l1 * sc1 + sum1;
        m0 = mn0;              m1 = mn1;

#pragma unroll
        for (int nt = 0; nt < 8; nt++) {
            oacc[nt][0] *= sc0; oacc[nt][1] *= sc0;
            oacc[nt][2] *= sc1; oacc[nt][3] *= sc1;
        }

        const uint32_t uVh = sb + (4 + 2 * vb) * ATB;
        const uint32_t uVl = uVh + ATB;
#pragma unroll
        for (int t = 0; t < 4; t++) {
            uint32_t ph[4], pl[4];
            {
                float p00 = sacc[2*t][0],   p01 = sacc[2*t][1];
                float p02 = sacc[2*t][2],   p03 = sacc[2*t][3];
                float p10 = sacc[2*t+1][0], p11 = sacc[2*t+1][1];
                float p12 = sacc[2*t+1][2], p13 = sacc[2*t+1][3];
                ph[0] = pack_bf16(p00, p01);
                ph[1] = pack_bf16(p02, p03);
                ph[2] = pack_bf16(p10, p11);
                ph[3] = pack_bf16(p12, p13);
                __nv_bfloat162* hp = reinterpret_cast<__nv_bfloat162*>(ph);
                pl[0] = pack_bf16(p00 - __bfloat162float(hp[0].x), p01 - __bfloat162float(hp[0].y));
                pl[1] = pack_bf16(p02 - __bfloat162float(hp[1].x), p03 - __bfloat162float(hp[1].y));
                pl[2] = pack_bf16(p10 - __bfloat162float(hp[2].x), p11 - __bfloat162float(hp[2].y));
                pl[3] = pack_bf16(p12 - __bfloat162float(hp[3].x), p13 - __bfloat162float(hp[3].y));
            }
            const uint32_t tb = (uint32_t)(t * 16 * AP * 2);
#pragma unroll
            for (int np = 0; np < 4; np++) {
                const uint32_t nb = (uint32_t)(np * 32);
                uint32_t vh[4], vl[4];
                ldmx4t(vh, uVh + voff + tb + nb);
                ldmx4t(vl, uVl + voff + tb + nb);
#pragma unroll
                for (int hh = 0; hh < 2; hh++) {
                    float* c = oacc[np * 2 + hh];
                    mma_bf16(c, ph, vh[hh * 2], vh[hh * 2 + 1]);
                    mma_bf16(c, pl, vh[hh * 2], vh[hh * 2 + 1]);
                    mma_bf16(c, ph, vl[hh * 2], vl[hh * 2 + 1]);
                }
            }
        }

        if (jb < qb) CPA_WAIT0();
        __syncthreads();
    }

    // ---- epilogue: write split bf16 attention output ----
    float li0 = 1.0f / l0, li1 = 1.0f / l1;
    const int col0 = (lane & 3) * 2;
#pragma unroll
    for (int nt = 0; nt < 8; nt++) {
        int c = nt * 8 + col0;
        float v0 = oacc[nt][0] * li0, v1 = oacc[nt][1] * li0;
        float v2 = oacc[nt][2] * li1, v3 = oacc[nt][3] * li1;
        uint32_t h01 = pack_bf16(v0, v1);
        uint32_t h23 = pack_bf16(v2, v3);
        __nv_bfloat162 hb01 = *reinterpret_cast<__nv_bfloat162*>(&h01);
        __nv_bfloat162 hb23 = *reinterpret_cast<__nv_bfloat162*>(&h23);
        uint32_t l01p = pack_bf16(v0 - __bfloat162float(hb01.x),
                                  v1 - __bfloat162float(hb01.y));
        uint32_t l23p = pack_bf16(v2 - __bfloat162float(hb23.x),
                                  v3 - __bfloat162float(hb23.y));
        *(uint32_t*)(ATh + base + (size_t)qg0 * DD + c) = h01;
        *(uint32_t*)(ATl + base + (size_t)qg0 * DD + c) = l01p;
        *(uint32_t*)(ATh + base + (size_t)qg1 * DD + c) = h23;
        *(uint32_t*)(ATl + base + (size_t)qg1 * DD + c) = l23p;
    }
}

// ---------------------------------------------------------------------------
// Launch
// ---------------------------------------------------------------------------
extern "C" void kernel_launch(void* const* d_in, const int* in_sizes, int n_in,
                              void* d_out, int out_size)
{
    const float* x  = (const float*)d_in[0];
    const float* wq = (const float*)d_in[1];
    const float* wk = (const float*)d_in[2];
    const float* wv = (const float*)d_in[3];
    const float* wo = (const float*)d_in[4];
    float* out = (float*)d_out;

    __nv_bfloat16 *xh, *xl, *wqh, *wql, *wkh, *wkl, *wvh, *wvl, *woh, *wol;
    __nv_bfloat16 *qh, *ql, *kh, *kl, *vh, *vl, *ath, *atl;
    cudaGetSymbolAddress((void**)&xh,  g_xh);  cudaGetSymbolAddress((void**)&xl,  g_xl);
    cudaGetSymbolAddress((void**)&wqh, g_wqh); cudaGetSymbolAddress((void**)&wql, g_wql);
    cudaGetSymbolAddress((void**)&wkh, g_wkh); cudaGetSymbolAddress((void**)&wkl, g_wkl);
    cudaGetSymbolAddress((void**)&wvh, g_wvh); cudaGetSymbolAddress((void**)&wvl, g_wvl);
    cudaGetSymbolAddress((void**)&woh, g_woh); cudaGetSymbolAddress((void**)&wol, g_wol);
    cudaGetSymbolAddress((void**)&qh,  g_qh);  cudaGetSymbolAddress((void**)&ql,  g_ql);
    cudaGetSymbolAddress((void**)&kh,  g_kh);  cudaGetSymbolAddress((void**)&kl,  g_kl);
    cudaGetSymbolAddress((void**)&vh,  g_vh);  cudaGetSymbolAddress((void**)&vl,  g_vl);
    cudaGetSymbolAddress((void**)&ath, g_ath); cudaGetSymbolAddress((void**)&atl, g_atl);

    cudaFuncSetAttribute(gemm_bf_qkv, cudaFuncAttributeMaxDynamicSharedMemorySize, GEMM_SMEM);
    cudaFuncSetAttribute(gemm_bf_f32, cudaFuncAttributeMaxDynamicSharedMemorySize, GEMM_SMEM);
    cudaFuncSetAttribute(attn_mma,    cudaFuncAttributeMaxDynamicSharedMemorySize, ATTN_SMEM_BYTES);

    // split inputs
    split_fp32<<<(MR * DD / 4 + 255) / 256, 256>>>(x,  xh,  xl,  MR * DD / 4);
    split_fp32<<<(DD * DD / 4 + 255) / 256, 256>>>(wq, wqh, wql, DD * DD / 4);
    split_fp32<<<(DD * DD / 4 + 255) / 256, 256>>>(wk, wkh, wkl, DD * DD / 4);
    split_fp32<<<(DD * DD / 4 + 255) / 256, 256>>>(wv, wvh, wvl, DD * DD / 4);
    split_fp32<<<(DD * DD / 4 + 255) / 256, 256>>>(wo, woh, wol, DD * DD / 4);

    dim3 qkvgrid(MR / 128, DD / 128, 3);
    gemm_bf_qkv<<<qkvgrid, 512, GEMM_SMEM>>>(xh, xl, wqh, wql, wkh, wkl, wvh, wvl,
                                             qh, ql, kh, kl, vh, vl);

    dim3 agrid(SS / 64, BB * HH);
    attn_mma<<<agrid, 128, ATTN_SMEM_BYTES>>>(qh, ql, kh, kl, vh, vl, ath, atl);

    dim3 ggrid(MR / 128, DD / 128);
    gemm_bf_f32<<<ggrid, 512, GEMM_SMEM>>>(ath, atl, woh, wol, out);
}

// round 8
// speedup vs baseline: 1.1820x; 1.1820x over previous
#include <cuda_runtime.h>
#include <cuda_bf16.h>
#include <math.h>
#include <stdint.h>

// Problem constants
#define BB   4
#define SS   2048
#define DD   1024
#define HH   16
#define HD   64
#define MR   (BB * SS)          // 8192 rows

// 0.125 * log2(e): folded softmax scale, base-2 domain
#define SCALE_LG2 0.18033688011112042f

// ---------------------------------------------------------------------------
// Scratch (device globals; no allocation allowed)
// ---------------------------------------------------------------------------
__device__ __nv_bfloat16 g_xh[8388608],  g_xl[8388608];
__device__ __nv_bfloat16 g_wqh[1048576], g_wql[1048576];
__device__ __nv_bfloat16 g_wkh[1048576], g_wkl[1048576];
__device__ __nv_bfloat16 g_wvh[1048576], g_wvl[1048576];
__device__ __nv_bfloat16 g_woh[1048576], g_wol[1048576];
__device__ __nv_bfloat16 g_qh[8388608], g_ql[8388608];
__device__ __nv_bfloat16 g_kh[8388608], g_kl[8388608];
__device__ __nv_bfloat16 g_vh[8388608], g_vl[8388608];
__device__ __nv_bfloat16 g_ath[8388608], g_atl[8388608];

// ---------------------------------------------------------------------------
// Helpers (plain sm_103-legal PTX: ldmatrix + mma.sync + cp.async)
// ---------------------------------------------------------------------------
__device__ __forceinline__ uint32_t smem_u32(const void* p) {
    uint32_t a;
    asm("{ .reg .u64 t; cvta.to.shared.u64 t, %1; cvt.u32.u64 %0, t; }" : "=r"(a) : "l"(p));
    return a;
}

__device__ __forceinline__ void ldmx4(uint32_t* r, uint32_t addr) {
    asm volatile("ldmatrix.sync.aligned.m8n8.x4.shared.b16 {%0,%1,%2,%3}, [%4];"
                 : "=r"(r[0]), "=r"(r[1]), "=r"(r[2]), "=r"(r[3]) : "r"(addr));
}

__device__ __forceinline__ void ldmx4t(uint32_t* r, uint32_t addr) {
    asm volatile("ldmatrix.sync.aligned.m8n8.x4.trans.shared.b16 {%0,%1,%2,%3}, [%4];"
                 : "=r"(r[0]), "=r"(r[1]), "=r"(r[2]), "=r"(r[3]) : "r"(addr));
}

__device__ __forceinline__ void mma_bf16(float* c, const uint32_t* a,
                                         uint32_t b0, uint32_t b1) {
    asm volatile(
        "mma.sync.aligned.m16n8k16.row.col.f32.bf16.bf16.f32 "
        "{%0,%1,%2,%3}, {%4,%5,%6,%7}, {%8,%9}, {%0,%1,%2,%3};"
        : "+f"(c[0]), "+f"(c[1]), "+f"(c[2]), "+f"(c[3])
        : "r"(a[0]), "r"(a[1]), "r"(a[2]), "r"(a[3]), "r"(b0), "r"(b1));
}

__device__ __forceinline__ void cpa16(uint32_t s, const void* g) {
    asm volatile("cp.async.ca.shared.global [%0], [%1], 16;" :: "r"(s), "l"(g) : "memory");
}
#define CPA_COMMIT() asm volatile("cp.async.commit_group;" ::: "memory")
#define CPA_WAIT0()  asm volatile("cp.async.wait_group 0;" ::: "memory")

__device__ __forceinline__ uint32_t pack_bf16(float x, float y) {
    __nv_bfloat162 t = __floats2bfloat162_rn(x, y);
    return *reinterpret_cast<uint32_t*>(&t);
}

// ---------------------------------------------------------------------------
// Split kernel: fp32 -> bf16 hi/lo (one float4 per thread)
// ---------------------------------------------------------------------------
__global__ void split_fp32(const float* __restrict__ src,
                           __nv_bfloat16* __restrict__ hi,
                           __nv_bfloat16* __restrict__ lo, int n4)
{
    int i = blockIdx.x * blockDim.x + threadIdx.x;
    if (i >= n4) return;
    float4 v = reinterpret_cast<const float4*>(src)[i];
    __nv_bfloat162 h01 = __floats2bfloat162_rn(v.x, v.y);
    __nv_bfloat162 h23 = __floats2bfloat162_rn(v.z, v.w);
    __nv_bfloat162 l01 = __floats2bfloat162_rn(v.x - __bfloat162float(h01.x),
                                               v.y - __bfloat162float(h01.y));
    __nv_bfloat162 l23 = __floats2bfloat162_rn(v.z - __bfloat162float(h23.x),
                                               v.w - __bfloat162float(h23.y));
    uint2 hh = make_uint2(*reinterpret_cast<uint32_t*>(&h01), *reinterpret_cast<uint32_t*>(&h23));
    uint2 ll = make_uint2(*reinterpret_cast<uint32_t*>(&l01), *reinterpret_cast<uint32_t*>(&l23));
    reinterpret_cast<uint2*>(hi)[i] = hh;
    reinterpret_cast<uint2*>(lo)[i] = ll;
}

// ---------------------------------------------------------------------------
// Pure-bf16 split HMMA GEMM, R6-proven schedule (LDG staging, no forced occ).
// C = (Ah+Al) @ (Bh+Bl)^T  via  D += Ah*Bh + Ah*Bl + Al*Bh.
// CTA tile 128x128, K-tile 32, 512 threads, warp tile 32x32.
// ---------------------------------------------------------------------------
#define GKP 40                        // padded row: 32 bf16 + 8 pad (80B)
#define GT  (128 * GKP)               // elems per tile
#define GSTAGE (4 * GT)               // Ah, Al, Bh, Bl
#define GEMM_SMEM (2 * GSTAGE * 2)    // 81920 B

#define GEMM_BF_BODY()                                                         \
    extern __shared__ __align__(16) char smem_raw[];                           \
    __nv_bfloat16* sm = reinterpret_cast<__nv_bfloat16*>(smem_raw);            \
    const uint32_t sb = smem_u32(sm);                                          \
    const int tid  = threadIdx.x;                                              \
    const int lane = tid & 31;                                                 \
    const int wid  = tid >> 5;                                                 \
    const int wm   = wid >> 2;                                                 \
    const int wn   = wid & 3;                                                  \
    const int bm   = blockIdx.x * 128;                                         \
    const int bn   = blockIdx.y * 128;                                         \
    const int lr = tid >> 2;                                                   \
    const int lc = (tid & 3) * 8;                                              \
    const __nv_bfloat16* Agh = Ah + (size_t)(bm + lr) * DD + lc;               \
    const __nv_bfloat16* Agl = Al + (size_t)(bm + lr) * DD + lc;               \
    const __nv_bfloat16* Bgh = Bh + (size_t)(bn + lr) * DD + lc;               \
    const __nv_bfloat16* Bgl = Bl + (size_t)(bn + lr) * DD + lc;               \
    uint4 rah, ral, rbh, rbl;                                                  \
    const uint32_t aoffB =                                                     \
        (uint32_t)(((wm * 32 + (lane & 15)) * GKP + (lane >> 4) * 8) * 2);     \
    const uint32_t boffB =                                                     \
        (uint32_t)(((wn * 32 + ((lane >> 4) << 3) + (lane & 7)) * GKP +        \
                    ((lane >> 3) & 1) * 8) * 2);                               \
    float acc[2][4][4];                                                        \
    _Pragma("unroll")                                                          \
    for (int mt = 0; mt < 2; mt++)                                             \
        _Pragma("unroll")                                                      \
        for (int nt = 0; nt < 4; nt++)                                         \
            _Pragma("unroll")                                                  \
            for (int i = 0; i < 4; i++) acc[mt][nt][i] = 0.f;                  \
    {                                                                          \
        rah = *(const uint4*)Agh;  ral = *(const uint4*)Agl;                   \
        rbh = *(const uint4*)Bgh;  rbl = *(const uint4*)Bgl;                   \
        int o = lr * GKP + lc;                                                 \
        *(uint4*)(sm + o)          = rah;                                      \
        *(uint4*)(sm + GT + o)     = ral;                                      \
        *(uint4*)(sm + 2 * GT + o) = rbh;                                      \
        *(uint4*)(sm + 3 * GT + o) = rbl;                                      \
    }                                                                          \
    __syncthreads();                                                           \
    _Pragma("unroll 1")                                                        \
    for (int kt = 0; kt < 32; kt++) {                                          \
        const int buf = kt & 1;                                                \
        if (kt + 1 < 32) {                                                     \
            const int ko = (kt + 1) * 32;                                      \
            rah = *(const uint4*)(Agh + ko);  ral = *(const uint4*)(Agl + ko); \
            rbh = *(const uint4*)(Bgh + ko);  rbl = *(const uint4*)(Bgl + ko); \
        }                                                                      \
        const uint32_t tA_h = sb + (uint32_t)(buf * GSTAGE * 2);               \
        const uint32_t tA_l = tA_h + GT * 2;                                   \
        const uint32_t tB_h = tA_h + 2 * GT * 2;                               \
        const uint32_t tB_l = tA_h + 3 * GT * 2;                               \
        _Pragma("unroll")                                                      \
        for (int ks = 0; ks < 2; ks++) {                                       \
            const uint32_t kb = ks * 32;                                       \
            uint32_t ah[2][4], al[2][4], bh2[2][4], bl2[2][4];                 \
            _Pragma("unroll")                                                  \
            for (int mt = 0; mt < 2; mt++) {                                   \
                ldmx4(ah[mt], tA_h + aoffB + mt * (16 * GKP * 2) + kb);        \
                ldmx4(al[mt], tA_l + aoffB + mt * (16 * GKP * 2) + kb);        \
            }                                                                  \
            _Pragma("unroll")                                                  \
            for (int nt2 = 0; nt2 < 2; nt2++) {                                \
                ldmx4(bh2[nt2], tB_h + boffB + nt2 * (16 * GKP * 2) + kb);     \
                ldmx4(bl2[nt2], tB_l + boffB + nt2 * (16 * GKP * 2) + kb);     \
            }                                                                  \
            _Pragma("unroll")                                                  \
            for (int mt = 0; mt < 2; mt++) {                                   \
                _Pragma("unroll")                                              \
                for (int nt2 = 0; nt2 < 2; nt2++) {                            \
                    _Pragma("unroll")                                          \
                    for (int h = 0; h < 2; h++) {                              \
                        float* c = acc[mt][nt2 * 2 + h];                       \
                        uint32_t b0h = bh2[nt2][h * 2], b1h = bh2[nt2][h * 2 + 1]; \
                        uint32_t b0l = bl2[nt2][h * 2], b1l = bl2[nt2][h * 2 + 1]; \
                        mma_bf16(c, ah[mt], b0h, b1h);                         \
                        mma_bf16(c, ah[mt], b0l, b1l);                         \
                        mma_bf16(c, al[mt], b0h, b1h);                         \
                    }                                                          \
                }                                                              \
            }                                                                  \
        }                                                                      \
        if (kt + 1 < 32) {                                                     \
            __nv_bfloat16* s = sm + (buf ^ 1) * GSTAGE;                        \
            int o = lr * GKP + lc;                                             \
            *(uint4*)(s + o)          = rah;                                   \
            *(uint4*)(s + GT + o)     = ral;                                   \
            *(uint4*)(s + 2 * GT + o) = rbh;                                   \
            *(uint4*)(s + 3 * GT + o) = rbl;                                   \
            __syncthreads();                                                   \
        }                                                                      \
    }

// fp32-output GEMM (final projection): A = att split, B = wo split
__global__ __launch_bounds__(512)
void gemm_bf_f32(const __nv_bfloat16* __restrict__ Ah, const __nv_bfloat16* __restrict__ Al,
                 const __nv_bfloat16* __restrict__ Bh, const __nv_bfloat16* __restrict__ Bl,
                 float* __restrict__ C)
{
    GEMM_BF_BODY();
#pragma unroll
    for (int mt = 0; mt < 2; mt++) {
#pragma unroll
        for (int nt = 0; nt < 4; nt++) {
            int r = bm + wm * 32 + mt * 16 + (lane >> 2);
            int c = bn + wn * 32 + nt * 8 + (lane & 3) * 2;
            *(float2*)(C + (size_t)r * DD + c)       = make_float2(acc[mt][nt][0], acc[mt][nt][1]);
            *(float2*)(C + (size_t)(r + 8) * DD + c) = make_float2(acc[mt][nt][2], acc[mt][nt][3]);
        }
    }
}

// Fused QKV projection: blockIdx.z selects weight & split-bf16 output.
__global__ __launch_bounds__(512)
void gemm_bf_qkv(const __nv_bfloat16* __restrict__ Xh, const __nv_bfloat16* __restrict__ Xl,
                 const __nv_bfloat16* __restrict__ Wqh, const __nv_bfloat16* __restrict__ Wql,
                 const __nv_bfloat16* __restrict__ Wkh, const __nv_bfloat16* __restrict__ Wkl,
                 const __nv_bfloat16* __restrict__ Wvh, const __nv_bfloat16* __restrict__ Wvl,
                 __nv_bfloat16* __restrict__ qh_, __nv_bfloat16* __restrict__ ql_,
                 __nv_bfloat16* __restrict__ kh_, __nv_bfloat16* __restrict__ kl_,
                 __nv_bfloat16* __restrict__ vh_, __nv_bfloat16* __restrict__ vl_)
{
    const __nv_bfloat16 *Ah = Xh, *Al = Xl, *Bh, *Bl;
    __nv_bfloat16 *Chi, *Clo;
    float alpha = 1.0f;
    if (blockIdx.z == 0)      { Bh = Wqh; Bl = Wql; Chi = qh_; Clo = ql_; alpha = SCALE_LG2; }
    else if (blockIdx.z == 1) { Bh = Wkh; Bl = Wkl; Chi = kh_; Clo = kl_; }
    else                      { Bh = Wvh; Bl = Wvl; Chi = vh_; Clo = vl_; }

    GEMM_BF_BODY();
#pragma unroll
    for (int mt = 0; mt < 2; mt++) {
#pragma unroll
        for (int nt = 0; nt < 4; nt++) {
            int r = bm + wm * 32 + mt * 16 + (lane >> 2);
            int c = bn + wn * 32 + nt * 8 + (lane & 3) * 2;
            float v0 = acc[mt][nt][0] * alpha, v1 = acc[mt][nt][1] * alpha;
            float v2 = acc[mt][nt][2] * alpha, v3 = acc[mt][nt][3] * alpha;
            uint32_t h01 = pack_bf16(v0, v1);
            uint32_t h23 = pack_bf16(v2, v3);
            __nv_bfloat162 hb01 = *reinterpret_cast<__nv_bfloat162*>(&h01);
            __nv_bfloat162 hb23 = *reinterpret_cast<__nv_bfloat162*>(&h23);
            uint32_t l01 = pack_bf16(v0 - __bfloat162float(hb01.x),
                                     v1 - __bfloat162float(hb01.y));
            uint32_t l23 = pack_bf16(v2 - __bfloat162float(hb23.x),
                                     v3 - __bfloat162float(hb23.y));
            *(uint32_t*)(Chi + (size_t)r * DD + c)       = h01;
            *(uint32_t*)(Chi + (size_t)(r + 8) * DD + c) = h23;
            *(uint32_t*)(Clo + (size_t)r * DD + c)       = l01;
            *(uint32_t*)(Clo + (size_t)(r + 8) * DD + c) = l23;
        }
    }
}

// ---------------------------------------------------------------------------
// Split-bf16 HMMA flash attention (R6-proven), epilogue writes split bf16.
// ---------------------------------------------------------------------------
#define AP 72
#define AT (64 * AP)
#define ATB (AT * 2)
#define ATTN_SMEM_BYTES (8 * ATB)     // 73728 -> 3 CTAs/SM

__global__ __launch_bounds__(128)
void attn_mma(const __nv_bfloat16* __restrict__ Qh, const __nv_bfloat16* __restrict__ Ql,
              const __nv_bfloat16* __restrict__ Kh, const __nv_bfloat16* __restrict__ Kl,
              const __nv_bfloat16* __restrict__ Vh, const __nv_bfloat16* __restrict__ Vl,
              __nv_bfloat16* __restrict__ ATh, __nv_bfloat16* __restrict__ ATl)
{
    extern __shared__ __align__(16) char asm_raw[];
    const uint32_t sb  = smem_u32(asm_raw);
    const uint32_t uQh = sb;
    const uint32_t uQl = sb + ATB;
    const uint32_t uKh = sb + 2 * ATB;
    const uint32_t uKl = sb + 3 * ATB;

    const int qb = (gridDim.x - 1) - blockIdx.x;   // heaviest first
    const int bh = blockIdx.y;
    const int b  = bh / HH;
    const int h  = bh % HH;
    const size_t base = (size_t)b * SS * DD + (size_t)h * HD;

    const int tid  = threadIdx.x;
    const int lane = tid & 31;
    const int w    = tid >> 5;

    const int comp = tid >> 6;
    const int crow = tid & 63;
    const __nv_bfloat16* Ksrc = comp ? Kl : Kh;
    const __nv_bfloat16* Vsrc = comp ? Vl : Vh;
    const uint32_t kdst = (comp ? uKl : uKh) + crow * AP * 2;
    const uint32_t rowoff = crow * AP * 2;

    {
        const __nv_bfloat16* src = comp ? Ql : Qh;
        const uint4* g = (const uint4*)(src + base + (size_t)(qb * 64 + crow) * DD);
        uint4* s = (uint4*)(asm_raw + comp * ATB + crow * AP * 2);
#pragma unroll
        for (int i = 0; i < 8; i++) s[i] = g[i];
    }
    {
        const __nv_bfloat16* gk = Ksrc + base + (size_t)crow * DD;
        const __nv_bfloat16* gv = Vsrc + base + (size_t)crow * DD;
        uint32_t vdst = sb + (4 + comp) * ATB + rowoff;
#pragma unroll
        for (int i = 0; i < 8; i++) cpa16(kdst + i * 16, gk + i * 8);
#pragma unroll
        for (int i = 0; i < 8; i++) cpa16(vdst + i * 16, gv + i * 8);
        CPA_COMMIT();
    }
    CPA_WAIT0();
    __syncthreads();

    const uint32_t aoff =
        (uint32_t)(((w * 16 + (lane & 15)) * AP + (lane >> 4) * 8) * 2);
    uint32_t qfh[4][4], qfl[4][4];
#pragma unroll
    for (int kk = 0; kk < 4; kk++) {
        ldmx4(qfh[kk], uQh + aoff + kk * 32);
        ldmx4(qfl[kk], uQl + aoff + kk * 32);
    }

    const uint32_t boff =
        (uint32_t)(((((lane >> 4) << 3) + (lane & 7)) * AP + ((lane >> 3) & 1) * 8) * 2);
    const uint32_t voff =
        (uint32_t)((((lane & 7) + ((lane >> 3) & 1) * 8) * AP) * 2 + (lane >> 4) * 16);

    const int r0  = lane >> 2;
    const int qg0 = qb * 64 + w * 16 + r0;
    const int qg1 = qg0 + 8;

    float m0 = -INFINITY, m1 = -INFINITY, l0 = 0.f, l1 = 0.f;
    float oacc[8][4];
#pragma unroll
    for (int nt = 0; nt < 8; nt++)
#pragma unroll
        for (int i = 0; i < 4; i++) oacc[nt][i] = 0.f;

#pragma unroll 1
    for (int jb = 0; jb <= qb; jb++) {
        const int vb = jb & 1;

        if (jb < qb) {
            const __nv_bfloat16* gv = Vsrc + base + (size_t)((jb + 1) * 64 + crow) * DD;
            uint32_t vdst = sb + (4 + 2 * (vb ^ 1) + comp) * ATB + rowoff;
#pragma unroll
            for (int i = 0; i < 8; i++) cpa16(vdst + i * 16, gv + i * 8);
            CPA_COMMIT();
        }

        float sacc[8][4];
#pragma unroll
        for (int nt = 0; nt < 8; nt++)
#pragma unroll
            for (int i = 0; i < 4; i++) sacc[nt][i] = 0.f;

#pragma unroll
        for (int kk = 0; kk < 4; kk++) {
            const uint32_t kb = kk * 32;
#pragma unroll
            for (int np = 0; np < 4; np++) {
                const uint32_t nb = (uint32_t)(np * 16 * AP * 2);
                uint32_t kh2[4], kl2[4];
                ldmx4(kh2, uKh + boff + nb + kb);
                ldmx4(kl2, uKl + boff + nb + kb);
#pragma unroll
                for (int hh = 0; hh < 2; hh++) {
                    float* c = sacc[np * 2 + hh];
                    mma_bf16(c, qfh[kk], kh2[hh * 2], kh2[hh * 2 + 1]);
                    mma_bf16(c, qfl[kk], kh2[hh * 2], kh2[hh * 2 + 1]);
                    mma_bf16(c, qfh[kk], kl2[hh * 2], kl2[hh * 2 + 1]);
                }
            }
        }
        __syncthreads();

        if (jb < qb) {
            const __nv_bfloat16* gk = Ksrc + base + (size_t)((jb + 1) * 64 + crow) * DD;
#pragma unroll
            for (int i = 0; i < 8; i++) cpa16(kdst + i * 16, gk + i * 8);
            CPA_COMMIT();
        }

        const int kvb = jb * 64 + (lane & 3) * 2;
        float mx0 = -INFINITY, mx1 = -INFINITY;
#pragma unroll
        for (int nt = 0; nt < 8; nt++) {
            int kg = kvb + nt * 8;
            float s0 = sacc[nt][0]; if (kg     > qg0) s0 = -INFINITY;
            float s1 = sacc[nt][1]; if (kg + 1 > qg0) s1 = -INFINITY;
            float s2 = sacc[nt][2]; if (kg     > qg1) s2 = -INFINITY;
            float s3 = sacc[nt][3]; if (kg + 1 > qg1) s3 = -INFINITY;
            sacc[nt][0] = s0; sacc[nt][1] = s1; sacc[nt][2] = s2; sacc[nt][3] = s3;
            mx0 = fmaxf(mx0, fmaxf(s0, s1));
            mx1 = fmaxf(mx1, fmaxf(s2, s3));
        }
        mx0 = fmaxf(mx0, __shfl_xor_sync(0xffffffff, mx0, 1));
        mx0 = fmaxf(mx0, __shfl_xor_sync(0xffffffff, mx0, 2));
        mx1 = fmaxf(mx1, __shfl_xor_sync(0xffffffff, mx1, 1));
        mx1 = fmaxf(mx1, __shfl_xor_sync(0xffffffff, mx1, 2));

        float mn0 = fmaxf(m0, mx0), mn1 = fmaxf(m1, mx1);
        float sc0 = exp2f(m0 - mn0), sc1 = exp2f(m1 - mn1);
        float sum0 = 0.f, sum1 = 0.f;
#pragma unroll
        for (int nt = 0; nt < 8; nt++) {
            float p0 = exp2f(sacc[nt][0] - mn0);
            float p1 = exp2f(sacc[nt][1] - mn0);
            float p2 = exp2f(sacc[nt][2] - mn1);
            float p3 = exp2f(sacc[nt][3] - mn1);
            sacc[nt][0] = p0; sacc[nt][1] = p1; sacc[nt][2] = p2; sacc[nt][3] = p3;
            sum0 += p0 + p1; sum1 += p2 + p3;
        }
        sum0 += __shfl_xor_sync(0xffffffff, sum0, 1);
        sum0 += __shfl_xor_sync(0xffffffff, sum0, 2);
        sum1 += __shfl_xor_sync(0xffffffff, sum1, 1);
        sum1 += __shfl_xor_sync(0xffffffff, sum1, 2);
        l0 = l0 * sc0 + sum0;  l1 = l1 * sc1 + sum1;
        m0 = mn0;              m1 = mn1;

#pragma unroll
        for (int nt = 0; nt < 8; nt++) {
            oacc[nt][0] *= sc0; oacc[nt][1] *= sc0;
            oacc[nt][2] *= sc1; oacc[nt][3] *= sc1;
        }

        const uint32_t uVh = sb + (4 + 2 * vb) * ATB;
        const uint32_t uVl = uVh + ATB;
#pragma unroll
        for (int t = 0; t < 4; t++) {
            uint32_t ph[4], pl[4];
            {
                float p00 = sacc[2*t][0],   p01 = sacc[2*t][1];
                float p02 = sacc[2*t][2],   p03 = sacc[2*t][3];
                float p10 = sacc[2*t+1][0], p11 = sacc[2*t+1][1];
                float p12 = sacc[2*t+1][2], p13 = sacc[2*t+1][3];
                ph[0] = pack_bf16(p00, p01);
                ph[1] = pack_bf16(p02, p03);
                ph[2] = pack_bf16(p10, p11);
                ph[3] = pack_bf16(p12, p13);
                __nv_bfloat162* hp = reinterpret_cast<__nv_bfloat162*>(ph);
                pl[0] = pack_bf16(p00 - __bfloat162float(hp[0].x), p01 - __bfloat162float(hp[0].y));
                pl[1] = pack_bf16(p02 - __bfloat162float(hp[1].x), p03 - __bfloat162float(hp[1].y));
                pl[2] = pack_bf16(p10 - __bfloat162float(hp[2].x), p11 - __bfloat162float(hp[2].y));
                pl[3] = pack_bf16(p12 - __bfloat162float(hp[3].x), p13 - __bfloat162float(hp[3].y));
            }
            const uint32_t tb = (uint32_t)(t * 16 * AP * 2);
#pragma unroll
            for (int np = 0; np < 4; np++) {
                const uint32_t nb = (uint32_t)(np * 32);
                uint32_t vh2[4], vl2[4];
                ldmx4t(vh2, uVh + voff + tb + nb);
                ldmx4t(vl2, uVl + voff + tb + nb);
#pragma unroll
                for (int hh = 0; hh < 2; hh++) {
                    float* c = oacc[np * 2 + hh];
                    mma_bf16(c, ph, vh2[hh * 2], vh2[hh * 2 + 1]);
                    mma_bf16(c, pl, vh2[hh * 2], vh2[hh * 2 + 1]);
                    mma_bf16(c, ph, vl2[hh * 2], vl2[hh * 2 + 1]);
                }
            }
        }

        if (jb < qb) CPA_WAIT0();
        __syncthreads();
    }

    // ---- epilogue: write split bf16 attention output ----
    float li0 = 1.0f / l0, li1 = 1.0f / l1;
    const int col0 = (lane & 3) * 2;
#pragma unroll
    for (int nt = 0; nt < 8; nt++) {
        int c = nt * 8 + col0;
        float v0 = oacc[nt][0] * li0, v1 = oacc[nt][1] * li0;
        float v2 = oacc[nt][2] * li1, v3 = oacc[nt][3] * li1;
        uint32_t h01 = pack_bf16(v0, v1);
        uint32_t h23 = pack_bf16(v2, v3);
        __nv_bfloat162 hb01 = *reinterpret_cast<__nv_bfloat162*>(&h01);
        __nv_bfloat162 hb23 = *reinterpret_cast<__nv_bfloat162*>(&h23);
        uint32_t l01p = pack_bf16(v0 - __bfloat162float(hb01.x),
                                  v1 - __bfloat162float(hb01.y));
        uint32_t l23p = pack_bf16(v2 - __bfloat162float(hb23.x),
                                  v3 - __bfloat162float(hb23.y));
        *(uint32_t*)(ATh + base + (size_t)qg0 * DD + c) = h01;
        *(uint32_t*)(ATl + base + (size_t)qg0 * DD + c) = l01p;
        *(uint32_t*)(ATh + base + (size_t)qg1 * DD + c) = h23;
        *(uint32_t*)(ATl + base + (size_t)qg1 * DD + c) = l23p;
    }
}

// ---------------------------------------------------------------------------
// Launch
// ---------------------------------------------------------------------------
extern "C" void kernel_launch(void* const* d_in, const int* in_sizes, int n_in,
                              void* d_out, int out_size)
{
    const float* x  = (const float*)d_in[0];
    const float* wq = (const float*)d_in[1];
    const float* wk = (const float*)d_in[2];
    const float* wv = (const float*)d_in[3];
    const float* wo = (const float*)d_in[4];
    float* out = (float*)d_out;

    __nv_bfloat16 *xh, *xl, *wqh, *wql, *wkh, *wkl, *wvh, *wvl, *woh, *wol;
    __nv_bfloat16 *qh, *ql, *kh, *kl, *vh, *vl, *ath, *atl;
    cudaGetSymbolAddress((void**)&xh,  g_xh);  cudaGetSymbolAddress((void**)&xl,  g_xl);
    cudaGetSymbolAddress((void**)&wqh, g_wqh); cudaGetSymbolAddress((void**)&wql, g_wql);
    cudaGetSymbolAddress((void**)&wkh, g_wkh); cudaGetSymbolAddress((void**)&wkl, g_wkl);
    cudaGetSymbolAddress((void**)&wvh, g_wvh); cudaGetSymbolAddress((void**)&wvl, g_wvl);
    cudaGetSymbolAddress((void**)&woh, g_woh); cudaGetSymbolAddress((void**)&wol, g_wol);
    cudaGetSymbolAddress((void**)&qh,  g_qh);  cudaGetSymbolAddress((void**)&ql,  g_ql);
    cudaGetSymbolAddress((void**)&kh,  g_kh);  cudaGetSymbolAddress((void**)&kl,  g_kl);
    cudaGetSymbolAddress((void**)&vh,  g_vh);  cudaGetSymbolAddress((void**)&vl,  g_vl);
    cudaGetSymbolAddress((void**)&ath, g_ath); cudaGetSymbolAddress((void**)&atl, g_atl);

    cudaFuncSetAttribute(gemm_bf_qkv, cudaFuncAttributeMaxDynamicSharedMemorySize, GEMM_SMEM);
    cudaFuncSetAttribute(gemm_bf_f32, cudaFuncAttributeMaxDynamicSharedMemorySize, GEMM_SMEM);
    cudaFuncSetAttribute(attn_mma,    cudaFuncAttributeMaxDynamicSharedMemorySize, ATTN_SMEM_BYTES);

    // split inputs
    split_fp32<<<(MR * DD / 4 + 255) / 256, 256>>>(x,  xh,  xl,  MR * DD / 4);
    split_fp32<<<(DD * DD / 4 + 255) / 256, 256>>>(wq, wqh, wql, DD * DD / 4);
    split_fp32<<<(DD * DD / 4 + 255) / 256, 256>>>(wk, wkh, wkl, DD * DD / 4);
    split_fp32<<<(DD * DD / 4 + 255) / 256, 256>>>(wv, wvh, wvl, DD * DD / 4);
    split_fp32<<<(DD * DD / 4 + 255) / 256, 256>>>(wo, woh, wol, DD * DD / 4);

    dim3 qkvgrid(MR / 128, DD / 128, 3);
    gemm_bf_qkv<<<qkvgrid, 512, GEMM_SMEM>>>(xh, xl, wqh, wql, wkh, wkl, wvh, wvl,
                                             qh, ql, kh, kl, vh, vl);

    dim3 agrid(SS / 64, BB * HH);
    attn_mma<<<agrid, 128, ATTN_SMEM_BYTES>>>(qh, ql, kh, kl, vh, vl, ath, atl);

    dim3 ggrid(MR / 128, DD / 128);
    gemm_bf_f32<<<ggrid, 512, GEMM_SMEM>>>(ath, atl, woh, wol, out);
}